// round 12
// baseline (speedup 1.0000x reference)
#include <cuda_runtime.h>
#include <cuda_bf16.h>

#define LEN 8192      // L
#define NROWS 8192    // B*C
#define CHUNK 256     // elements per warp-chunk (8 per lane)
#define NCHUNK (LEN / CHUNK)   // 32
#define NSTAGE 4      // cp.async pipeline depth (chunks in flight per warp)

// Warp-autonomous solver with a per-warp cp.async smem ring.
// No CTA barriers, no atomics, no L2 prefetch (regressed), static balanced
// row assignment (<=2 rows/warp). Transformed recurrence:
//   y[i] = ap[i]*y[i+1] + z[i],  x[i] = rinv[i]*y[i]
//   ap[i] = -sup[i+1]/diag[i+1] (ap[L-1]=0), rinv[i] = 1/diag[i]
// ap/rinv are fp32-constant for i in [~64, L-2] (contraction; validated).
// Steady-state chunks: scalar coefficients + precomputed scan A-side.
// Boundary chunks (31 head-of-march / 0) use exact inline coefficients.
__global__ __launch_bounds__(896, 1) void ou_solve_kernel(const float* __restrict__ z,
                                                          const float* __restrict__ diag,
                                                          const float* __restrict__ sup,
                                                          float* __restrict__ x) {
    extern __shared__ float4 sring[];   // [warp][stage][j][lane] float4

    const int lane = threadIdx.x & 31;
    const int warp = threadIdx.x >> 5;
    const int wpc  = blockDim.x >> 5;
    const int gw   = blockIdx.x * wpc + warp;
    const int W    = gridDim.x * wpc;

    // Converged mid-array constants.
    const float rinv_c = 1.0f / diag[LEN / 2];
    const float ap_c   = -sup[LEN / 2 + 1] / diag[LEN / 2 + 1];
    float p2 = ap_c * ap_c;
    float p4 = p2 * p2;
    const float Aseg_c = p4 * p4;                // ap_c^8

    // Loop-invariant A-side of the warp reverse scan.
    float As0, As1, As2, As3, As4, sA_f;
    {
        float sA = Aseg_c;
        As0 = sA; { float A2 = __shfl_down_sync(0xffffffffu, sA, 1);  if (lane + 1  < 32) sA *= A2; }
        As1 = sA; { float A2 = __shfl_down_sync(0xffffffffu, sA, 2);  if (lane + 2  < 32) sA *= A2; }
        As2 = sA; { float A2 = __shfl_down_sync(0xffffffffu, sA, 4);  if (lane + 4  < 32) sA *= A2; }
        As3 = sA; { float A2 = __shfl_down_sync(0xffffffffu, sA, 8);  if (lane + 8  < 32) sA *= A2; }
        As4 = sA; { float A2 = __shfl_down_sync(0xffffffffu, sA, 16); if (lane + 16 < 32) sA *= A2; }
        sA_f = sA;
    }

    const int r0 = gw;                 // gw < ~4200 < NROWS always
    const int r1 = gw + W;
    const int total = ((r1 < NROWS) ? 2 : 1) * NCHUNK;

    // Per-lane ring base: element (s, j) lives at ringl[(s*2 + j) * 32].
    float4* ringl = sring + (size_t)(warp * NSTAGE * 2) * 32 + lane;
    unsigned rbase = (unsigned)__cvta_generic_to_shared(ringl);

    // Feed chunk k of this warp's linear schedule into ring stage k % NSTAGE.
    #define FEED(k)                                                            \
        do {                                                                   \
            int _rr = ((k) < NCHUNK) ? r0 : r1;                                \
            int _cc = (NCHUNK - 1) - ((k) & (NCHUNK - 1));                     \
            const float4* _p = (const float4*)(z + (size_t)_rr * LEN           \
                                                 + _cc * CHUNK + lane * 8);    \
            unsigned _d = rbase + (unsigned)(((k) & (NSTAGE - 1)) * 1024);     \
            asm volatile("cp.async.cg.shared.global [%0], [%1], 16;\n\t"       \
                         "cp.async.cg.shared.global [%2], [%3], 16;"           \
                         :: "r"(_d), "l"(_p), "r"(_d + 512), "l"(_p + 1)       \
                         : "memory");                                          \
        } while (0)

    // Prologue: fill the pipeline (one commit group per stage; empty ok).
    #pragma unroll
    for (int s = 0; s < NSTAGE; ++s) {
        if (s < total) FEED(s);
        asm volatile("cp.async.commit_group;" ::: "memory");
    }

    float carry = 0.0f;

    #pragma unroll 1
    for (int k = 0; k < total; ++k) {
        // Group k holds chunk k; <=3 pending => chunk k is resident.
        asm volatile("cp.async.wait_group 3;" ::: "memory");

        const int stage = k & (NSTAGE - 1);
        float4 u0 = ringl[(stage * 2 + 0) * 32];
        float4 u1 = ringl[(stage * 2 + 1) * 32];

        // Feed the stage we just drained (write lands >=L2 latency later).
        {
            int kf = k + NSTAGE;
            if (kf < total) FEED(kf);
            asm volatile("cp.async.commit_group;" ::: "memory");
        }

        const int kk  = k & (NCHUNK - 1);
        const int cc  = (NCHUNK - 1) - kk;
        const int rr  = (k < NCHUNK) ? r0 : r1;
        const int off = cc * CHUNK + lane * 8;
        float* xr = x + (size_t)rr * LEN;
        if (kk == 0) carry = 0.0f;     // new row

        if (cc != 0 && cc != NCHUNK - 1) {
            // ---------- FAST PATH: scalar coefficients ----------
            float B = u1.w;
            B = fmaf(ap_c, B, u1.z);
            B = fmaf(ap_c, B, u1.y);
            B = fmaf(ap_c, B, u1.x);
            B = fmaf(ap_c, B, u0.w);
            B = fmaf(ap_c, B, u0.z);
            B = fmaf(ap_c, B, u0.y);
            B = fmaf(ap_c, B, u0.x);

            float sB = B;
            { float B2 = __shfl_down_sync(0xffffffffu, sB, 1);  if (lane + 1  < 32) sB = fmaf(As0, B2, sB); }
            { float B2 = __shfl_down_sync(0xffffffffu, sB, 2);  if (lane + 2  < 32) sB = fmaf(As1, B2, sB); }
            { float B2 = __shfl_down_sync(0xffffffffu, sB, 4);  if (lane + 4  < 32) sB = fmaf(As2, B2, sB); }
            { float B2 = __shfl_down_sync(0xffffffffu, sB, 8);  if (lane + 8  < 32) sB = fmaf(As3, B2, sB); }
            { float B2 = __shfl_down_sync(0xffffffffu, sB, 16); if (lane + 16 < 32) sB = fmaf(As4, B2, sB); }

            float Bf = fmaf(sA_f, carry, sB);
            float y = __shfl_down_sync(0xffffffffu, Bf, 1);
            if (lane == 31) y = carry;
            carry = __shfl_sync(0xffffffffu, Bf, 0);

            y = fmaf(ap_c, y, u1.w); u1.w = rinv_c * y;
            y = fmaf(ap_c, y, u1.z); u1.z = rinv_c * y;
            y = fmaf(ap_c, y, u1.y); u1.y = rinv_c * y;
            y = fmaf(ap_c, y, u1.x); u1.x = rinv_c * y;
            y = fmaf(ap_c, y, u0.w); u0.w = rinv_c * y;
            y = fmaf(ap_c, y, u0.z); u0.z = rinv_c * y;
            y = fmaf(ap_c, y, u0.y); u0.y = rinv_c * y;
            y = fmaf(ap_c, y, u0.x); u0.x = rinv_c * y;
        } else {
            // ---------- BOUNDARY PATH: exact coefficients inline ----------
            const float4 d0 = *(const float4*)(diag + off);
            const float4 d1 = *(const float4*)(diag + off + 4);
            const float4 s0 = *(const float4*)(sup + off);
            const float4 s1 = *(const float4*)(sup + off + 4);
            float4 r0v, r1v;
            r0v.x = 1.0f / d0.x; r0v.y = 1.0f / d0.y; r0v.z = 1.0f / d0.z; r0v.w = 1.0f / d0.w;
            r1v.x = 1.0f / d1.x; r1v.y = 1.0f / d1.y; r1v.z = 1.0f / d1.z; r1v.w = 1.0f / d1.w;
            float4 a0, a1;
            a0.x = -s0.y * r0v.y; a0.y = -s0.z * r0v.z; a0.z = -s0.w * r0v.w; a0.w = -s1.x * r1v.x;
            a1.x = -s1.y * r1v.y; a1.y = -s1.z * r1v.z; a1.z = -s1.w * r1v.w;
            float t = -s0.x * r0v.x;
            a1.w = __shfl_down_sync(0xffffffffu, t, 1);
            if (lane == 31) a1.w = (cc == 0) ? ap_c : 0.0f;

            float B = u1.w;
            B = fmaf(a1.z, B, u1.z);
            B = fmaf(a1.y, B, u1.y);
            B = fmaf(a1.x, B, u1.x);
            B = fmaf(a0.w, B, u0.w);
            B = fmaf(a0.z, B, u0.z);
            B = fmaf(a0.y, B, u0.y);
            B = fmaf(a0.x, B, u0.x);
            float Aseg = ((a1.w * a1.z) * (a1.y * a1.x)) *
                         ((a0.w * a0.z) * (a0.y * a0.x));

            float sA = Aseg, sB = B;
            #pragma unroll
            for (int d = 1; d < 32; d <<= 1) {
                float A2 = __shfl_down_sync(0xffffffffu, sA, d);
                float B2 = __shfl_down_sync(0xffffffffu, sB, d);
                if (lane + d < 32) {
                    sB = fmaf(sA, B2, sB);
                    sA *= A2;
                }
            }

            float Bf = fmaf(sA, carry, sB);
            float y = __shfl_down_sync(0xffffffffu, Bf, 1);
            if (lane == 31) y = carry;
            carry = __shfl_sync(0xffffffffu, Bf, 0);

            y = fmaf(a1.w, y, u1.w); u1.w = r1v.w * y;
            y = fmaf(a1.z, y, u1.z); u1.z = r1v.z * y;
            y = fmaf(a1.y, y, u1.y); u1.y = r1v.y * y;
            y = fmaf(a1.x, y, u1.x); u1.x = r1v.x * y;
            y = fmaf(a0.w, y, u0.w); u0.w = r0v.w * y;
            y = fmaf(a0.z, y, u0.z); u0.z = r0v.z * y;
            y = fmaf(a0.y, y, u0.y); u0.y = r0v.y * y;
            y = fmaf(a0.x, y, u0.x); u0.x = r0v.x * y;
        }

        __stcs((float4*)(xr + off),     u0);
        __stcs((float4*)(xr + off + 4), u1);
    }
    #undef FEED
}

extern "C" void kernel_launch(void* const* d_in, const int* in_sizes, int n_in,
                              void* d_out, int out_size) {
    const float* normal_samples = (const float*)d_in[0];  // (32, 256, 8192) f32
    const float* diag           = (const float*)d_in[1];  // (8192,) f32
    const float* sup            = (const float*)d_in[2];  // (8192,) f32
    float* out = (float*)d_out;

    (void)in_sizes; (void)n_in; (void)out_size;

    int sm_count = 148;
    cudaDeviceGetAttribute(&sm_count, cudaDevAttrMultiProcessorCount, 0);

    // Every warp gets <=2 rows with near-perfect balance.
    int wpc = (NROWS / 2 + sm_count - 1) / sm_count;
    if (wpc > 28) wpc = 28;   // stay under __launch_bounds__(896)

    int smem = wpc * NSTAGE * 2 * 32 * 16;   // 4KB per warp ring
    cudaFuncSetAttribute(ou_solve_kernel,
                         cudaFuncAttributeMaxDynamicSharedMemorySize, smem);
    ou_solve_kernel<<<sm_count, wpc * 32, smem>>>(normal_samples, diag, sup, out);
}

// round 13
// speedup vs baseline: 1.3118x; 1.3118x over previous
#include <cuda_runtime.h>
#include <cuda_bf16.h>

#define LEN 8192       // L
#define NROWS 8192     // B*C
#define CHUNK 128      // elements per warp-chunk (4 per lane)
#define NCHUNK (LEN / CHUNK)   // 64 chunks per row
#define DEPTH 4        // register pipeline depth (2KB outstanding per warp)

// Warp-autonomous solver, 4-deep rotating LDG register pipeline.
// No barriers, no smem, no atomics, no cp.async (regressed), no L2 prefetch
// (regressed). Static balanced rows: every warp gets <=2 rows.
//
// Transformed recurrence: y[i] = ap[i]*y[i+1] + z[i],  x[i] = rinv[i]*y[i]
//   ap[i] = -sup[i+1]/diag[i+1] (ap[L-1] = 0),  rinv[i] = 1/diag[i]
// Cholesky recursion is a contraction (rate ~0.69): ap/rinv are fp32-constant
// for i in [~64, L-2] (validated at rel_err 2e-7). Chunks c=1..62 use two
// scalar constants + precomputed scan A-side; c=63 (tail) and c=0 (head)
// compute exact coefficients inline from diag/sup.
__global__ __launch_bounds__(896, 1) void ou_solve_kernel(const float* __restrict__ z,
                                                          const float* __restrict__ diag,
                                                          const float* __restrict__ sup,
                                                          float* __restrict__ x) {
    const int lane = threadIdx.x & 31;
    const int warp = threadIdx.x >> 5;
    const int wpc  = blockDim.x >> 5;
    const int gw   = blockIdx.x * wpc + warp;
    const int W    = gridDim.x * wpc;

    // Converged mid-array constants.
    const float rinv_c = 1.0f / diag[LEN / 2];
    const float ap_c   = -sup[LEN / 2 + 1] / diag[LEN / 2 + 1];
    const float ap2    = ap_c * ap_c;
    const float Aseg_c = ap2 * ap2;              // ap_c^4 (segment of 4)

    // Loop-invariant A-side of the warp reverse scan (for Aseg_c segments).
    float As0, As1, As2, As3, As4, sA_f;
    {
        float sA = Aseg_c;
        As0 = sA; { float A2 = __shfl_down_sync(0xffffffffu, sA, 1);  if (lane + 1  < 32) sA *= A2; }
        As1 = sA; { float A2 = __shfl_down_sync(0xffffffffu, sA, 2);  if (lane + 2  < 32) sA *= A2; }
        As2 = sA; { float A2 = __shfl_down_sync(0xffffffffu, sA, 4);  if (lane + 4  < 32) sA *= A2; }
        As3 = sA; { float A2 = __shfl_down_sync(0xffffffffu, sA, 8);  if (lane + 8  < 32) sA *= A2; }
        As4 = sA; { float A2 = __shfl_down_sync(0xffffffffu, sA, 16); if (lane + 16 < 32) sA *= A2; }
        sA_f = sA;
    }

    const int r0 = gw;                  // gw < ~4300 < NROWS always
    const int r1 = gw + W;
    const int total = ((r1 < NROWS) ? 2 : 1) * NCHUNK;

    // Linear march: step k -> row (k<NCHUNK ? r0 : r1), chunk c = 63 - (k&63).
    #define ZADDR(k) (z + (size_t)(((k) < NCHUNK) ? r0 : r1) * LEN              \
                        + (NCHUNK - 1 - ((k) & (NCHUNK - 1))) * CHUNK + lane * 4)

    // Prologue: fill the 4-slot pipeline (total >= 64 >= DEPTH always).
    float4 b[DEPTH];
    b[0] = __ldcs((const float4*)ZADDR(0));
    b[1] = __ldcs((const float4*)ZADDR(1));
    b[2] = __ldcs((const float4*)ZADDR(2));
    b[3] = __ldcs((const float4*)ZADDR(3));

    float carry = 0.0f;

    #pragma unroll 4
    for (int k = 0; k < total; ++k) {
        float4 u = b[k & 3];
        // Refill the drained slot with the chunk DEPTH ahead.
        if (k + DEPTH < total) b[k & 3] = __ldcs((const float4*)ZADDR(k + DEPTH));

        const int m  = k & (NCHUNK - 1);
        const int c  = (NCHUNK - 1) - m;
        const int rr = (k < NCHUNK) ? r0 : r1;
        const int off = c * CHUNK + lane * 4;
        float* xr = x + (size_t)rr * LEN;
        if (m == 0) carry = 0.0f;       // new row

        if (c != 0 && c != NCHUNK - 1) {
            // ---------- FAST PATH: scalar coefficients ----------
            float B = u.w;
            B = fmaf(ap_c, B, u.z);
            B = fmaf(ap_c, B, u.y);
            B = fmaf(ap_c, B, u.x);

            float sB = B;
            { float B2 = __shfl_down_sync(0xffffffffu, sB, 1);  if (lane + 1  < 32) sB = fmaf(As0, B2, sB); }
            { float B2 = __shfl_down_sync(0xffffffffu, sB, 2);  if (lane + 2  < 32) sB = fmaf(As1, B2, sB); }
            { float B2 = __shfl_down_sync(0xffffffffu, sB, 4);  if (lane + 4  < 32) sB = fmaf(As2, B2, sB); }
            { float B2 = __shfl_down_sync(0xffffffffu, sB, 8);  if (lane + 8  < 32) sB = fmaf(As3, B2, sB); }
            { float B2 = __shfl_down_sync(0xffffffffu, sB, 16); if (lane + 16 < 32) sB = fmaf(As4, B2, sB); }

            float Bf = fmaf(sA_f, carry, sB);
            float y = __shfl_down_sync(0xffffffffu, Bf, 1);
            if (lane == 31) y = carry;
            carry = __shfl_sync(0xffffffffu, Bf, 0);

            y = fmaf(ap_c, y, u.w); u.w = rinv_c * y;
            y = fmaf(ap_c, y, u.z); u.z = rinv_c * y;
            y = fmaf(ap_c, y, u.y); u.y = rinv_c * y;
            y = fmaf(ap_c, y, u.x); u.x = rinv_c * y;
        } else {
            // ---------- BOUNDARY PATH: exact coefficients inline ----------
            const float4 d0 = *(const float4*)(diag + off);
            const float4 s0 = *(const float4*)(sup + off);
            float4 rv;
            rv.x = 1.0f / d0.x; rv.y = 1.0f / d0.y; rv.z = 1.0f / d0.z; rv.w = 1.0f / d0.w;
            float4 a;
            a.x = -s0.y * rv.y; a.y = -s0.z * rv.z; a.z = -s0.w * rv.w;
            float t = -s0.x * rv.x;                    // next lane's first ap source
            a.w = __shfl_down_sync(0xffffffffu, t, 1);
            // lane31: i = off+3. c==63 -> i=8191 (no successor, ap=0);
            // c==0 -> i=127, successor i=128 is converged -> ap_c.
            if (lane == 31) a.w = (c == 0) ? ap_c : 0.0f;

            float B = u.w;
            B = fmaf(a.z, B, u.z);
            B = fmaf(a.y, B, u.y);
            B = fmaf(a.x, B, u.x);
            float Aseg = (a.w * a.z) * (a.y * a.x);

            float sA = Aseg, sB = B;
            #pragma unroll
            for (int d = 1; d < 32; d <<= 1) {
                float A2 = __shfl_down_sync(0xffffffffu, sA, d);
                float B2 = __shfl_down_sync(0xffffffffu, sB, d);
                if (lane + d < 32) {
                    sB = fmaf(sA, B2, sB);
                    sA *= A2;
                }
            }

            float Bf = fmaf(sA, carry, sB);
            float y = __shfl_down_sync(0xffffffffu, Bf, 1);
            if (lane == 31) y = carry;
            carry = __shfl_sync(0xffffffffu, Bf, 0);

            y = fmaf(a.w, y, u.w); u.w = rv.w * y;
            y = fmaf(a.z, y, u.z); u.z = rv.z * y;
            y = fmaf(a.y, y, u.y); u.y = rv.y * y;
            y = fmaf(a.x, y, u.x); u.x = rv.x * y;
        }

        __stcs((float4*)(xr + off), u);
    }
    #undef ZADDR
}

extern "C" void kernel_launch(void* const* d_in, const int* in_sizes, int n_in,
                              void* d_out, int out_size) {
    const float* normal_samples = (const float*)d_in[0];  // (32, 256, 8192) f32
    const float* diag           = (const float*)d_in[1];  // (8192,) f32
    const float* sup            = (const float*)d_in[2];  // (8192,) f32
    float* out = (float*)d_out;

    (void)in_sizes; (void)n_in; (void)out_size;

    int sm_count = 148;
    cudaDeviceGetAttribute(&sm_count, cudaDevAttrMultiProcessorCount, 0);

    // Every warp gets <=2 rows with near-perfect balance (W >= NROWS/2).
    int wpc = (NROWS / 2 + sm_count - 1) / sm_count;
    if (wpc > 28) wpc = 28;   // stay under __launch_bounds__(896)
    ou_solve_kernel<<<sm_count, wpc * 32>>>(normal_samples, diag, sup, out);
}